// round 17
// baseline (speedup 1.0000x reference)
#include <cuda_runtime.h>
#include <cuda_fp16.h>
#include <cstdint>

#define BB 4096
#define MAXN 12
#define HID 301
#define NT 10
#define PP 9
#define VSTAT 310
#define KP 320          // padded hidden (= unique K)
#define KS 640          // activation storage: [hi(320) | lo(320)] fp16
#define JT 80           // j-cols per block -> grid 32 x 4 = 128 blocks (occ 1)
#define NJ 4
#define KC 32           // unique-K per chunk
#define NCH 10          // 320/32
#define SROW 40         // staged smem row stride in halves (80B)
#define THR 512
#define SW 328          // persistent weight row stride in halves (656B; ldsm conflict-free)

#define A1_H (128 * SROW)               // 5120 halves (one A half-tile)
#define WH_H (240 * SW)                 // 78720 halves persistent Whh slice
#define ASTG_H (2 * A1_H)               // 10240 halves (A hi+lo stage)
#define GSTG_H (ASTG_H + 160 * SROW)    // 16640 halves (gate stage: A + B)
#define SM_MAIN ((WH_H + 2 * GSTG_H) * 2)   // 224000 B

// ---------------- scratch (device globals; zero-initialized) ----------------
__device__ __align__(16) float d_g[(size_t)BB * 11 * KP];
__device__ __align__(16) float d_hcur[(size_t)BB * KP];
__device__ __align__(16) float d_hin[(size_t)BB * KP];
__device__ __align__(16) __half d_hAS[(size_t)BB * KS];
__device__ __align__(16) __half d_iAS[(size_t)BB * KS];
__device__ __align__(16) __half d_WhhS[960 * KP];   // rows s*320+j
__device__ __align__(16) __half d_WgmS[640 * KP];   // rows m*320+j
__device__ unsigned d_bar[32 * 24];
// epilogue tables (coalesced in j)
__device__ __align__(16) float d_T1[NT * 3 * KP];
__device__ __align__(16) float d_T2[PP * 3 * KP];
__device__ __align__(16) float d_bhh3[3 * KP];
__device__ __align__(16) float d_Tg[PP * KP];
__device__ __align__(16) float d_Tm[PP * KP];
// head GEMM weights
__device__ __align__(16) float d_Wfc[128 * KP];
__device__ __align__(16) float d_bfc[128];

__device__ __forceinline__ float sigm(float x) { return 1.f / (1.f + __expf(-x)); }
__device__ __forceinline__ void hsplit(float x, __half& hi, __half& lo) {
    hi = __float2half_rn(x);
    lo = __float2half_rn(x - __half2float(hi));
}
__device__ __forceinline__ void mma_f16(float c[4], const uint32_t a[4],
                                        uint32_t b0, uint32_t b1) {
    asm volatile(
        "mma.sync.aligned.m16n8k16.row.col.f32.f16.f16.f32 "
        "{%0,%1,%2,%3}, {%4,%5,%6,%7}, {%8,%9}, {%0,%1,%2,%3};"
        : "+f"(c[0]), "+f"(c[1]), "+f"(c[2]), "+f"(c[3])
        : "r"(a[0]), "r"(a[1]), "r"(a[2]), "r"(a[3]), "r"(b0), "r"(b1));
}
__device__ __forceinline__ void ldsm4(uint32_t* r, uint32_t addr) {
    asm volatile("ldmatrix.sync.aligned.m8n8.x4.shared.b16 {%0,%1,%2,%3}, [%4];"
                 : "=r"(r[0]), "=r"(r[1]), "=r"(r[2]), "=r"(r[3]) : "r"(addr));
}
__device__ __forceinline__ void ldsm2(uint32_t* r, uint32_t addr) {
    asm volatile("ldmatrix.sync.aligned.m8n8.x2.shared.b16 {%0,%1}, [%2];"
                 : "=r"(r[0]), "=r"(r[1]) : "r"(addr));
}
__device__ __forceinline__ void cpa16(uint32_t s, const void* g) {
    asm volatile("cp.async.ca.shared.global [%0], [%1], 16;" :: "r"(s), "l"(g));
}
#define CP_COMMIT() asm volatile("cp.async.commit_group;")
template<int N> __device__ __forceinline__ void cp_wait() {
    asm volatile("cp.async.wait_group %0;" :: "n"(N));
}

// per-batch-tile barrier among the NJ=4 j-blocks of bx.
__device__ __forceinline__ void barx(int bx, int k) {
    __syncthreads();
    if (threadIdx.x == 0) {
        __threadfence();
        unsigned* c = &d_bar[bx * 24 + k];
        unsigned old = atomicAdd(c, 1u);
        unsigned target = (old & ~3u) + 4u;
        while (atomicAdd(c, 0u) < target) { __nanosleep(64); }
        __threadfence();
    }
    __syncthreads();
}

// ---------------- weight repack (fp16, UNIQUE K) ----------------------------
__global__ void k_pad(const float* __restrict__ Whh, const float* __restrict__ Wg,
                      const float* __restrict__ Wm)
{
    int idx = blockIdx.x * blockDim.x + threadIdx.x;
    const int total = HID * HID;
    if (idx < 3 * total) {
        int s = idx / total, r = idx - s * total, j = r / HID, k = r - j * HID;
        d_WhhS[(size_t)(s * KP + j) * KP + k] = __float2half_rn(Whh[(s * HID + j) * HID + k]);
    } else if (idx < 5 * total) {
        int m = (idx - 3 * total) / total, r = (idx - 3 * total) % total;
        int j = r / HID, k = r - j * HID;
        const float* W = m ? Wm : Wg;
        d_WgmS[(size_t)(m * KP + j) * KP + k] = __float2half_rn(W[j * VSTAT + k]);
    }
}

// ---------------- epilogue table build --------------------------------------
__global__ void k_tab(const float* __restrict__ W_ih, const float* __restrict__ b_ih,
                      const float* __restrict__ b_hh,
                      const float* __restrict__ Wg, const float* __restrict__ bg,
                      const float* __restrict__ Wm)
{
    int idx = blockIdx.x * blockDim.x + threadIdx.x;
    const int TPK = 3 * KP;
    if (idx < NT * TPK) {
        int t = idx / TPK, r = idx - t * TPK, s = r / KP, j = r - s * KP;
        d_T1[idx] = (j < HID) ? W_ih[(size_t)(s * HID + j) * 19 + t] + b_ih[s * HID + j] : 0.f;
    } else if (idx < NT * TPK + PP * TPK) {
        int q = idx - NT * TPK;
        int p = q / TPK, r = q - p * TPK, s = r / KP, j = r - s * KP;
        d_T2[q] = (j < HID) ? W_ih[(size_t)(s * HID + j) * 19 + NT + p] : 0.f;
    } else if (idx < NT * TPK + PP * TPK + TPK) {
        int q = idx - NT * TPK - PP * TPK;
        int s = q / KP, j = q - s * KP;
        d_bhh3[q] = (j < HID) ? b_hh[s * HID + j] : 0.f;
    } else if (idx < NT * TPK + PP * TPK + TPK + PP * KP) {
        int q = idx - NT * TPK - PP * TPK - TPK;
        int p = q / KP, j = q - p * KP;
        d_Tg[q] = (j < HID) ? Wg[(size_t)j * VSTAT + HID + p] + bg[j] : 0.f;
    } else if (idx < NT * TPK + PP * TPK + TPK + 2 * PP * KP) {
        int q = idx - NT * TPK - PP * TPK - TPK - PP * KP;
        int p = q / KP, j = q - p * KP;
        d_Tm[q] = (j < HID) ? Wm[(size_t)j * VSTAT + HID + p] : 0.f;
    }
}

// ---------------- head weight pad build -------------------------------------
__global__ void k_wfc(const float* __restrict__ W_fc1, const float* __restrict__ b_fc1,
                      const float* __restrict__ W_fc2, const float* __restrict__ b_fc2)
{
    int idx = blockIdx.x * blockDim.x + threadIdx.x;
    if (idx < 112 * KP) {
        int o = idx / KP, k = idx - o * KP;
        float v = 0.f;
        if (k < HID + 8)
            v = (o < 56) ? W_fc1[o * (HID + 8) + k] : W_fc2[(o - 56) * (HID + 8) + k];
        d_Wfc[o * KP + k] = v;
    } else if (idx < 112 * KP + 112) {
        int o = idx - 112 * KP;
        d_bfc[o] = (o < 56) ? b_fc1[o] : b_fc2[o - 56];
    }
}

// ============================================================================
// Persistent recurrence kernel. Grid 32 x 4, 512 threads, occ 1.
// Whh j-slice resident in smem for the whole kernel; GRU streams only A.
// ============================================================================
__global__ void __launch_bounds__(THR, 1) k_main(
    const int* __restrict__ types, const int* __restrict__ paths,
    const int* __restrict__ adj)
{
    extern __shared__ __half sm[];
    int tid = threadIdx.x, lane = tid & 31, wid = tid >> 5;
    int g = lane >> 2, tig = lane & 3;
    int li = lane >> 3, lt = lane & 7;
    int wm = wid >> 1, wn = wid & 1;
    int bx = blockIdx.x, jy = blockIdx.y;
    int b0 = bx * 128, j0 = jy * JT;

    uint32_t sbase = (uint32_t)__cvta_generic_to_shared(sm);
    const uint32_t stgbase = sbase + WH_H * 2;    // staging region base (bytes)

    // fragment offsets
    uint32_t aoffH, aoffL;                         // relative to stage base
    uint32_t bfG[6], bfG2[3];                      // absolute (persistent weights)
    uint32_t bfT[4], bfT2[2];                      // relative to gate stage base
    {
        int mrow = wm * 16 + (li & 1) * 8 + lt;
        aoffH = (uint32_t)(mrow * SROW + (li >> 1) * 8) * 2;
        aoffL = aoffH + A1_H * 2;
    }
#pragma unroll
    for (int s = 0; s < 3; ++s) {
#pragma unroll
        for (int part = 0; part < 2; ++part) {
            int nrow = s * JT + wn * 40 + part * 16 + (li >> 1) * 8 + lt;
            bfG[s * 2 + part] = sbase + (uint32_t)nrow * SW * 2 + (lane & 1) * 0 + (uint32_t)(li & 1) * 16;
        }
        int nrow2 = s * JT + wn * 40 + 32 + lt;
        bfG2[s] = sbase + (uint32_t)nrow2 * SW * 2 + (uint32_t)((lane >> 3) & 1) * 16;
    }
#pragma unroll
    for (int s = 0; s < 2; ++s) {
#pragma unroll
        for (int part = 0; part < 2; ++part) {
            int nrow = s * JT + wn * 40 + part * 16 + (li >> 1) * 8 + lt;
            bfT[s * 2 + part] = (uint32_t)(ASTG_H + nrow * SROW + (li & 1) * 8) * 2;
        }
        int nrow2 = s * JT + wn * 40 + 32 + lt;
        bfT2[s] = (uint32_t)(ASTG_H + nrow2 * SROW) * 2 + (uint32_t)((lane >> 3) & 1) * 16;
    }

    // ---- one-time: stage persistent Whh slice (overlapped with h0 phase) ----
    for (int idx = tid; idx < 240 * 40; idx += THR) {
        int r = idx / 40, sg = idx - r * 40;       // r: 0..239, sg: 0..39 (16B segs)
        int s = r / JT, jt = r - s * JT;
        cpa16(sbase + (uint32_t)r * SW * 2 + sg * 16,
              d_WhhS + (size_t)(s * KP + j0 + jt) * KP + sg * 8);
    }
    CP_COMMIT();

    // ---------------- phase: h0 (global-memory only) ----------------
    for (int idx = tid; idx < 128 * JT; idx += THR) {
        int r = idx / JT, jj = idx - r * JT;
        int j = j0 + jj;
        if (j >= HID) continue;
        int b = b0 + r;
        int t = types[b * MAXN], p = paths[b * MAXN];
        const float* t1 = d_T1 + t * 3 * KP;
        const float* t2 = d_T2 + p * 3 * KP;
        float rr = sigm(t1[j] + t2[j] + d_bhh3[j]);
        float zz = sigm(t1[KP + j] + t2[KP + j] + d_bhh3[KP + j]);
        float nn = tanhf(t1[2 * KP + j] + t2[2 * KP + j] + rr * d_bhh3[2 * KP + j]);
        float h = (1.f - zz) * nn;
        d_hcur[(size_t)b * KP + j] = h;
        __half hi, lo; hsplit(h, hi, lo);
        size_t o = (size_t)b * KS + j;
        d_hAS[o] = hi; d_hAS[o + KP] = lo;
    }
    cp_wait<0>();
    barx(bx, 0);

    for (int v = 0; v < 11; ++v) {
        // ================= gate(v) phase (2-stage: A + streamed B) ==========
        {
            float c[10][4];
#pragma unroll
            for (int nf = 0; nf < 10; ++nf)
#pragma unroll
                for (int i = 0; i < 4; ++i) c[nf][i] = 0.f;

            auto loadChunkT = [&](int st, int ci) {
                uint32_t sa = stgbase + st * (GSTG_H * 2);
                int k0 = ci * KC;
#pragma unroll
                for (int q = 0; q < 2; ++q) {           // A hi+lo: 1024 ops
                    int idx = tid + THR * q;
                    int half = idx >> 9;
                    int i2 = idx & 511;
                    int r = i2 >> 2, sg = i2 & 3;
                    cpa16(sa + (half * A1_H + r * SROW + sg * 8) * 2,
                          d_hAS + (size_t)(b0 + r) * KS + half * KP + k0 + sg * 8);
                }
#pragma unroll
                for (int q = 0; q < 2; ++q) {           // B: 160 rows x 4 = 640
                    int idx = tid + THR * q;
                    if (idx < 640) {
                        int r = idx >> 2, sg = idx & 3;
                        int s = r / JT, jt = r - s * JT;
                        cpa16(sa + (ASTG_H + r * SROW + sg * 8) * 2,
                              d_WgmS + (size_t)(s * KP + j0 + jt) * KP + k0 + sg * 8);
                    }
                }
            };

            loadChunkT(0, 0); CP_COMMIT();
            loadChunkT(1, 1); CP_COMMIT();

#pragma unroll 1
            for (int ci = 0; ci < NCH; ++ci) {
                if (ci < NCH - 1) cp_wait<1>(); else cp_wait<0>();
                __syncthreads();
                uint32_t stg = stgbase + (ci & 1) * (GSTG_H * 2);
#pragma unroll
                for (int k16 = 0; k16 < 2; ++k16) {
                    uint32_t ko2 = (uint32_t)k16 * 32;
                    uint32_t ah[4], al[4];
                    ldsm4(ah, stg + aoffH + ko2);
                    ldsm4(al, stg + aoffL + ko2);
#pragma unroll
                    for (int s = 0; s < 2; ++s) {
                        uint32_t bb[4];
                        ldsm4(bb, stg + bfT[s * 2] + ko2);
                        mma_f16(c[s * 5 + 0], ah, bb[0], bb[1]);
                        mma_f16(c[s * 5 + 0], al, bb[0], bb[1]);
                        mma_f16(c[s * 5 + 1], ah, bb[2], bb[3]);
                        mma_f16(c[s * 5 + 1], al, bb[2], bb[3]);
                        ldsm4(bb, stg + bfT[s * 2 + 1] + ko2);
                        mma_f16(c[s * 5 + 2], ah, bb[0], bb[1]);
                        mma_f16(c[s * 5 + 2], al, bb[0], bb[1]);
                        mma_f16(c[s * 5 + 3], ah, bb[2], bb[3]);
                        mma_f16(c[s * 5 + 3], al, bb[2], bb[3]);
                        uint32_t b2[2];
                        ldsm2(b2, stg + bfT2[s] + ko2);
                        mma_f16(c[s * 5 + 4], ah, b2[0], b2[1]);
                        mma_f16(c[s * 5 + 4], al, b2[0], b2[1]);
                    }
                }
                __syncthreads();
                if (ci + 2 < NCH) { loadChunkT(ci & 1, ci + 2); CP_COMMIT(); }
            }

            // ---- epilogue: d_g direct from accumulators ----
            float* hin_s = (float*)((char*)sm + WH_H * 2);     // [128][80]
            float* adjf  = hin_s + 128 * JT;                   // [128][12]
#pragma unroll
            for (int hf = 0; hf < 2; ++hf) {
                int row = wm * 16 + g + hf * 8;
                int p = paths[(b0 + row) * MAXN + v];
                const float* tg = d_Tg + p * KP;
                const float* tm = d_Tm + p * KP;
#pragma unroll
                for (int nf = 0; nf < 5; ++nf) {
                    int jb = j0 + wn * 40 + nf * 8 + 2 * tig;
                    float v2[2];
#pragma unroll
                    for (int cl = 0; cl < 2; ++cl) {
                        int j = jb + cl;
                        int ci2 = hf * 2 + cl;
                        float val = 0.f;
                        if (j < HID) {
                            float gv = sigm(c[nf][ci2] + tg[j]);
                            float mv = c[nf + 5][ci2] + tm[j];
                            val = gv * mv;
                        }
                        v2[cl] = val;
                    }
                    *(float2*)&d_g[((size_t)(b0 + row) * 11 + v) * KP + jb] =
                        make_float2(v2[0], v2[1]);
                }
            }
            for (int idx = tid; idx < 128 * MAXN; idx += THR) {
                int r = idx / MAXN, u = idx - r * MAXN;
                adjf[idx] = (float)adj[(size_t)(b0 + r) * (MAXN * MAXN) + (v + 1) * MAXN + u];
            }
            __syncthreads();

            for (int idx = tid; idx < 128 * JT; idx += THR) {
                int r = idx / JT, jj = idx - r * JT;
                float acc = 0.f;
                for (int u = 0; u <= v; ++u) {
                    if (adjf[r * MAXN + u] != 0.f)
                        acc += d_g[((size_t)(b0 + r) * 11 + u) * KP + j0 + jj];
                }
                hin_s[idx] = acc;
            }
            __syncthreads();

            for (int idx = tid; idx < 128 * (JT / 4); idx += THR) {
                int r = idx / (JT / 4), sg = idx - r * (JT / 4);
                float4 h4 = *(float4*)&hin_s[r * JT + sg * 4];
                *(float4*)&d_hin[(size_t)(b0 + r) * KP + j0 + sg * 4] = h4;
                __half h0, l0, h1, l1, h2, l2, h3, l3;
                hsplit(h4.x, h0, l0); hsplit(h4.y, h1, l1);
                hsplit(h4.z, h2, l2); hsplit(h4.w, h3, l3);
                size_t o = (size_t)(b0 + r) * KS + j0 + sg * 4;
                __half2* ph_ = (__half2*)(d_iAS + o);
                ph_[0] = __half2{h0, h1}; ph_[1] = __half2{h2, h3};
                __half2* pl_ = (__half2*)(d_iAS + o + KP);
                pl_[0] = __half2{l0, l1}; pl_[1] = __half2{l2, l3};
            }
        }
        barx(bx, 1 + 2 * v);

        // ================= gru(v+1) phase (A-only stream, B resident) =======
        {
            int vv = v + 1;
            float c[15][4];
#pragma unroll
            for (int nf = 0; nf < 15; ++nf)
#pragma unroll
                for (int i = 0; i < 4; ++i) c[nf][i] = 0.f;

            auto loadChunkG = [&](int st, int ci) {
                uint32_t sa = stgbase + st * (ASTG_H * 2);
                int k0 = ci * KC;
#pragma unroll
                for (int q = 0; q < 2; ++q) {           // A hi+lo: 1024 ops
                    int idx = tid + THR * q;
                    int half = idx >> 9;
                    int i2 = idx & 511;
                    int r = i2 >> 2, sg = i2 & 3;
                    cpa16(sa + (half * A1_H + r * SROW + sg * 8) * 2,
                          d_iAS + (size_t)(b0 + r) * KS + half * KP + k0 + sg * 8);
                }
            };

            loadChunkG(0, 0); CP_COMMIT();
            loadChunkG(1, 1); CP_COMMIT();

#pragma unroll 1
            for (int ci = 0; ci < NCH; ++ci) {
                if (ci < NCH - 1) cp_wait<1>(); else cp_wait<0>();
                __syncthreads();
                if (ci + 2 < NCH) { loadChunkG((ci + 2) % 3, ci + 2); CP_COMMIT(); }
                uint32_t stgA = stgbase + (ci % 3) * (ASTG_H * 2);
                uint32_t kw = (uint32_t)ci * 64;        // weight col offset (bytes)
#pragma unroll
                for (int k16 = 0; k16 < 2; ++k16) {
                    uint32_t ko2 = (uint32_t)k16 * 32;
                    uint32_t ah[4], al[4];
                    ldsm4(ah, stgA + aoffH + ko2);
                    ldsm4(al, stgA + aoffL + ko2);
#pragma unroll
                    for (int s = 0; s < 3; ++s) {
                        uint32_t bb[4];
                        ldsm4(bb, bfG[s * 2] + kw + ko2);
                        mma_f16(c[s * 5 + 0], ah, bb[0], bb[1]);
                        mma_f16(c[s * 5 + 0], al, bb[0], bb[1]);
                        mma_f16(c[s * 5 + 1], ah, bb[2], bb[3]);
                        mma_f16(c[s * 5 + 1], al, bb[2], bb[3]);
                        ldsm4(bb, bfG[s * 2 + 1] + kw + ko2);
                        mma_f16(c[s * 5 + 2], ah, bb[0], bb[1]);
                        mma_f16(c[s * 5 + 2], al, bb[0], bb[1]);
                        mma_f16(c[s * 5 + 3], ah, bb[2], bb[3]);
                        mma_f16(c[s * 5 + 3], al, bb[2], bb[3]);
                        uint32_t b2[2];
                        ldsm2(b2, bfG2[s] + kw + ko2);
                        mma_f16(c[s * 5 + 4], ah, b2[0], b2[1]);
                        mma_f16(c[s * 5 + 4], al, b2[0], b2[1]);
                    }
                }
            }

            // ---- fused GRU epilogue (register-resident r/z/n) ----
#pragma unroll
            for (int hf = 0; hf < 2; ++hf) {
                int row = b0 + wm * 16 + g + hf * 8;
                int t = types[row * MAXN + vv], p = paths[row * MAXN + vv];
                const float* t1 = d_T1 + t * 3 * KP;
                const float* t2 = d_T2 + p * 3 * KP;
#pragma unroll
                for (int nf = 0; nf < 5; ++nf) {
                    int jb = j0 + wn * 40 + nf * 8 + 2 * tig;
                    float h2[2];
#pragma unroll
                    for (int cl = 0; cl < 2; ++cl) {
                        int j = jb + cl;
                        int ci2 = hf * 2 + cl;
                        float h = 0.f;
                        if (j < HID) {
                            float hin = d_hin[(size_t)row * KP + j];
                            float rr = sigm(c[nf][ci2] + t1[j] + t2[j] + d_bhh3[j]);
                            float zz = sigm(c[nf + 5][ci2] + t1[KP + j] + t2[KP + j] +
                                            d_bhh3[KP + j]);
                            float nn = tanhf(t1[2 * KP + j] + t2[2 * KP + j] +
                                             rr * (c[nf + 10][ci2] + d_bhh3[2 * KP + j]));
                            h = (1.f - zz) * nn + zz * hin;
                        }
                        h2[cl] = h;
                    }
                    *(float2*)&d_hcur[(size_t)row * KP + jb] = make_float2(h2[0], h2[1]);
                    __half h0h, h0l, h1h, h1l;
                    hsplit(h2[0], h0h, h0l); hsplit(h2[1], h1h, h1l);
                    size_t o = (size_t)row * KS + jb;
                    *(__half2*)(d_hAS + o)      = __half2{h0h, h1h};
                    *(__half2*)(d_hAS + o + KP) = __half2{h0l, h1l};
                }
            }
        }
        if (v < 10) barx(bx, 2 + 2 * v);
    }
}

// ---------------- head pre: df scatter + tiny MLPs -> d_hcur[b][301..309) ---
__global__ void __launch_bounds__(256) k_headpre(
    const int* __restrict__ paths, const float* __restrict__ feats,
    const float* __restrict__ W_df1, const float* __restrict__ b_df1,
    const float* __restrict__ W_df2, const float* __restrict__ b_df2)
{
    __shared__ float sdf[8][28];
    __shared__ float s16[8][16];
    int lane = threadIdx.x & 31, w = threadIdx.x >> 5;
    int b = blockIdx.x * 8 + w;

    if (lane < 27) sdf[w][lane] = 0.f;
    __syncwarp();
    if (lane == 0) {
        for (int v = 0; v < MAXN; ++v) {
            int base = paths[b * MAXN + v] * 3;
            sdf[w][base]     = feats[(b * MAXN + v) * 3 + 0];
            sdf[w][base + 1] = feats[(b * MAXN + v) * 3 + 1];
            sdf[w][base + 2] = feats[(b * MAXN + v) * 3 + 2];
        }
    }
    __syncwarp();
    if (lane < 16) {
        float a = b_df1[lane];
        for (int k = 0; k < 27; ++k) a = fmaf(sdf[w][k], W_df1[lane * 27 + k], a);
        s16[w][lane] = fmaxf(a, 0.f);
    }
    __syncwarp();
    if (lane < 8) {
        float a = b_df2[lane];
        for (int k = 0; k < 16; ++k) a = fmaf(s16[w][k], W_df2[lane * 16 + k], a);
        d_hcur[(size_t)b * KP + HID + lane] = a;
    }
}

// ---------------- head GEMM: out[4096,112] = hcur[4096,320] @ Wfc^T + b -----
__global__ void __launch_bounds__(256) k_fc(float* __restrict__ out)
{
    __shared__ float4 sA[64][8];
    __shared__ float4 sW[64][9];
    int tid = threadIdx.x;
    int tx = tid & 31, ty = tid >> 5;
    int b0 = blockIdx.x * 64;
    int c0 = blockIdx.y * 64;

    float acc[8][2];
#pragma unroll
    for (int i = 0; i < 8; ++i) { acc[i][0] = 0.f; acc[i][1] = 0.f; }

    for (int k0 = 0; k0 < KP; k0 += 32) {
#pragma unroll
        for (int q = 0; q < 2; ++q) {
            int idx = tid + 256 * q;
            int r = idx >> 3, cc = idx & 7;
            sA[r][cc] = *(const float4*)&d_hcur[(size_t)(b0 + r) * KP + k0 + 4 * cc];
            sW[r][cc] = *(const float4*)&d_Wfc[(size_t)(c0 + r) * KP + k0 + 4 * cc];
        }
        __syncthreads();
#pragma unroll
        for (int kq = 0; kq < 8; ++kq) {
            float4 w0 = sW[tx][kq], w1 = sW[tx + 32][kq];
#pragma unroll
            for (int i = 0; i < 8; ++i) {
                float4 a = sA[ty + 8 * i][kq];
                acc[i][0] = fmaf(a.x, w0.x, acc[i][0]); acc[i][0] = fmaf(a.y, w0.y, acc[i][0]);
                acc[i][0] = fmaf(a.z, w0.z, acc[i][0]); acc[i][0] = fmaf(a.w, w0.w, acc[i][0]);
                acc[i][1] = fmaf(a.x, w1.x, acc[i][1]); acc[i][1] = fmaf(a.y, w1.y, acc[i][1]);
                acc[i][1] = fmaf(a.z, w1.z, acc[i][1]); acc[i][1] = fmaf(a.w, w1.w, acc[i][1]);
            }
        }
        __syncthreads();
    }

    int c1 = c0 + tx, c2 = c0 + tx + 32;
#pragma unroll
    for (int i = 0; i < 8; ++i) {
        int row = b0 + ty + 8 * i;
        if (c1 < 112) out[(size_t)row * 112 + c1] = acc[i][0] + d_bfc[c1];
        if (c2 < 112) out[(size_t)row * 112 + c2] = acc[i][1] + d_bfc[c2];
    }
}

// ---------------- launcher --------------------------------------------------
extern "C" void kernel_launch(void* const* d_in, const int* in_sizes, int n_in,
                              void* d_out, int out_size)
{
    const int*   types = (const int*)d_in[0];
    const int*   paths = (const int*)d_in[1];
    const int*   adj   = (const int*)d_in[2];
    const float* feats = (const float*)d_in[3];
    const float* W_ih  = (const float*)d_in[4];
    const float* W_hh  = (const float*)d_in[5];
    const float* b_ih  = (const float*)d_in[6];
    const float* b_hh  = (const float*)d_in[7];
    const float* Wg    = (const float*)d_in[8];
    const float* bg    = (const float*)d_in[9];
    const float* Wm    = (const float*)d_in[10];
    const float* W_df1 = (const float*)d_in[11];
    const float* b_df1 = (const float*)d_in[12];
    const float* W_df2 = (const float*)d_in[13];
    const float* b_df2 = (const float*)d_in[14];
    const float* W_fc1 = (const float*)d_in[15];
    const float* b_fc1 = (const float*)d_in[16];
    const float* W_fc2 = (const float*)d_in[17];
    const float* b_fc2 = (const float*)d_in[18];
    float* out = (float*)d_out;

    cudaFuncSetAttribute(k_main, cudaFuncAttributeMaxDynamicSharedMemorySize, SM_MAIN);

    const int tabN = NT * 3 * KP + PP * 3 * KP + 3 * KP + 2 * PP * KP;
    k_pad<<<(5 * HID * HID + 255) / 256, 256>>>(W_hh, Wg, Wm);
    k_tab<<<(tabN + 255) / 256, 256>>>(W_ih, b_ih, b_hh, Wg, bg, Wm);
    k_wfc<<<(112 * KP + 112 + 255) / 256, 256>>>(W_fc1, b_fc1, W_fc2, b_fc2);

    dim3 grid(32, NJ);   // 128 blocks, occ 1 -> all co-resident
    k_main<<<grid, THR, SM_MAIN>>>(types, paths, adj);

    k_headpre<<<BB / 8, 256>>>(paths, feats, W_df1, b_df1, W_df2, b_df2);
    dim3 gFC(BB / 64, 2);
    k_fc<<<gFC, 256>>>(out);
}